// round 6
// baseline (speedup 1.0000x reference)
#include <cuda_runtime.h>
#include <cstdint>

// Problem: B=8, C=256, H=W=64, K=3, pad=1, stride=1
// out_flat[f] = keyflat[f] * qv[f/9], f in [0, 9*4096) per (b,c) slice
//   keyflat[f] = zero-padded key at (l>>6 + kk/3 - 1, (l&63) + kk%3 - 1)
//   qv[l']     = zero-padded query at fq = 9*l'+4 (same patch formula)
// CTA = (slice bc, dr-group g): handles kk = 3g..3g+2. dr == g is constant.
#define HW     64
#define KPITCH 68                 // key rows pitch: 64 data + halo col0 + col65 + 2 pad
#define KROWS  64                 // padded rows g..g+63 (local 0..63)
#define KWORDS (KROWS * KPITCH)   // 4352
#define LSZ    4096
#define QVN    1368               // qv window: 1367 entries used, padded

__global__ void __launch_bounds__(256)
appearance_kernel(const float* __restrict__ key,
                  const float* __restrict__ query,
                  float* __restrict__ out) {
    __shared__ alignas(16) float krows[KWORDS];  // 17408 B
    __shared__ alignas(16) float qv[QVN];        //  5472 B

    const int tid = threadIdx.x;
    const int bid = blockIdx.x;          // 0..6143
    const int bc  = bid / 3;             // slice 0..2047
    const int g   = bid - bc * 3;        // dr group 0..2

    const float* kb = key   + (size_t)bc * LSZ;
    const float* qb = query + (size_t)bc * LSZ;

    // ---- load key rows: local row r holds padded row (r+g) = image row (r+g-1) ----
    // cols: image col c at local col c+1; col 0 and cols 65..67 are zero halo.
    {
        // zero halo columns (4 words x 64 rows = 256 words, one per thread)
        const int r = tid >> 2, hc = tid & 3;        // hc -> cols {0,65,66,67}
        krows[r * KPITCH + (hc == 0 ? 0 : 64 + hc)] = 0.0f;
    }
    #pragma unroll
    for (int k = 0; k < 4; k++) {
        const int i  = tid + k * 256;    // 0..1023 float4 tiles
        const int r  = i >> 4;           // local row 0..63
        const int c4 = i & 15;           // float4 col within row
        const int r_img = r + g - 1;
        float4 v = make_float4(0.f, 0.f, 0.f, 0.f);
        if ((unsigned)r_img < (unsigned)HW)
            v = *(const float4*)(kb + r_img * HW + c4 * 4);
        float* p = &krows[r * KPITCH + 1 + c4 * 4];
        p[0] = v.x; p[1] = v.y; p[2] = v.z; p[3] = v.w;
    }

    // ---- qv window: l' in [qlo, qlo+1366], direct bounds-checked LDG ----
    const int qlo = (g * 12288) / 9;     // 0, 1365, 2730
    #pragma unroll
    for (int k = 0; k < 6; k++) {
        const int jj = tid + k * 256;
        if (jj < QVN) {
            const int lp = qlo + jj;
            float v = 0.0f;
            if (lp < LSZ) {
                const int fq  = 9 * lp + 4;
                const int kkq = fq >> 12;
                const int lq  = fq & 4095;
                const int row = (lq >> 6) + kkq / 3 - 1;
                const int col = (lq & 63) + kkq % 3 - 1;
                if (((unsigned)row < (unsigned)HW) & ((unsigned)col < (unsigned)HW))
                    v = __ldg(qb + row * HW + col);
            }
            qv[jj] = v;
        }
    }
    __syncthreads();

    // ---- main loop: 12 float4 outputs per thread (3 kk x 4 it) ----
    float4* out4 = (float4*)out + (size_t)bc * 9216;
    const int l0  = tid << 2;            // multiple of 4
    const int row = l0 >> 6;
    const int col = l0 & 63;             // multiple of 4 -> 16B aligned window

    #pragma unroll
    for (int it = 0; it < 4; it++) {
        // window: local row (row + it*16), cols col..col+5 (dr folded into krows)
        const float* wp = &krows[(row + it * 16) * KPITCH + col];
        const float4 a = *(const float4*)wp;        // w0..w3
        const float2 b = *(const float2*)(wp + 4);  // w4,w5
        const float w0 = a.x, w1 = a.y, w2 = a.z, w3 = a.w, w4 = b.x, w5 = b.y;

        #pragma unroll
        for (int dc = 0; dc < 3; dc++) {
            const int kk = 3 * g + dc;
            const int f  = kk * LSZ + it * 1024 + l0;
            const unsigned lp0 = (unsigned)f / 9u;  // mul-hi
            const int rem = f - (int)lp0 * 9;       // 0..8
            const float q0 = qv[lp0 - qlo];
            const float q1 = qv[lp0 - qlo + 1];

            float4 o;
            o.x = (dc == 0 ? w0 : dc == 1 ? w1 : w2) * q0;
            o.y = (dc == 0 ? w1 : dc == 1 ? w2 : w3) * (rem >= 8 ? q1 : q0);
            o.z = (dc == 0 ? w2 : dc == 1 ? w3 : w4) * (rem >= 7 ? q1 : q0);
            o.w = (dc == 0 ? w3 : dc == 1 ? w4 : w5) * (rem >= 6 ? q1 : q0);
            out4[kk * 1024 + it * 256 + tid] = o;
        }
    }
}

extern "C" void kernel_launch(void* const* d_in, const int* in_sizes, int n_in,
                              void* d_out, int out_size) {
    const float* key   = (const float*)d_in[0];
    const float* query = (const float*)d_in[1];
    float* out = (float*)d_out;

    appearance_kernel<<<6144, 256>>>(key, query, out);
}

// round 7
// speedup vs baseline: 1.0957x; 1.0957x over previous
#include <cuda_runtime.h>
#include <cstdint>

// Problem: B=8, C=256, H=W=64, K=3, pad=1, stride=1
// out_flat[f] = keyflat[f] * qv[f/9], f in [0, 9*4096) per (b,c) slice
//   keyflat[f] = zero-padded key at (l>>6 + kk/3 - 1, (l&63) + kk%3 - 1)
//   qv[l']     = zero-padded query at fq = 9*l'+4 (same patch formula)
// CTA = (slice bc, quarter q): handles l in [q*1024, q*1024+1024), all 9 kk.
#define HW   64
#define KP   68                 // key tile pitch (1 left halo + 64 + 3 right pad)
#define KR   18                 // image rows q*16-1 .. q*16+16
#define KTW  (KR * KP)          // 1224 words
#define QW   116                // qv window entries per kk
#define QVT  (9 * QW)           // 1044 words
#define LSZ  4096

__global__ void __launch_bounds__(256)
appearance_kernel(const float* __restrict__ key,
                  const float* __restrict__ query,
                  float* __restrict__ out) {
    __shared__ alignas(16) float ktile[KTW];   // 4896 B
    __shared__ alignas(16) float qvs[QVT];     // 4176 B

    const int tid = threadIdx.x;
    const int bid = blockIdx.x;        // 0..8191
    const int bc  = bid >> 2;          // slice 0..2047
    const int q   = bid & 3;           // quarter 0..3
    const int q1024 = q << 10;

    const float*  kb  = key   + (size_t)bc * LSZ;
    const float4* kb4 = (const float4*)kb;
    const float*  qb  = query + (size_t)bc * LSZ;

    // ---- zero halo columns (cols 0, 65, 66, 67 of all 18 rows) ----
    if (tid < KR * 4) {
        const int lr = tid >> 2, hc = tid & 3;
        ktile[lr * KP + (hc == 0 ? 0 : 64 + hc)] = 0.0f;
    }

    // ---- key tile: local row lr = image row (q*16 - 1 + lr) ----
    #pragma unroll
    for (int k = 0; k < 2; k++) {
        const int i = tid + k * 256;               // 0..511, need 288
        if (i < KR * 16) {
            const int lr = i >> 4, c4 = i & 15;
            const int ir = q * 16 - 1 + lr;
            float4 v = make_float4(0.f, 0.f, 0.f, 0.f);
            if ((unsigned)ir < (unsigned)HW) v = kb4[ir * 16 + c4];
            float* p = &ktile[lr * KP + 1 + c4 * 4];   // +1: unaligned, scalar STS
            p[0] = v.x; p[1] = v.y; p[2] = v.z; p[3] = v.w;
        }
    }

    // ---- qv windows: qvs[kk*QW + j] = qv[base(kk) + j], base = (kk*4096+q*1024)/9 ----
    #pragma unroll
    for (int k = 0; k < 5; k++) {
        const int j = tid + k * 256;               // 0..1279, need 1044
        if (j < QVT) {
            const int kk = (unsigned)j / QW;
            const int jj = j - kk * QW;
            const int lp = (unsigned)(kk * LSZ + q1024) / 9u + jj;
            float v = 0.0f;
            if (lp < LSZ) {
                const int fq  = 9 * lp + 4;
                const int kkq = fq >> 12;
                const int lq  = fq & 4095;
                const int row = (lq >> 6) + kkq / 3 - 1;
                const int col = (lq & 63) + kkq % 3 - 1;
                if (((unsigned)row < (unsigned)HW) & ((unsigned)col < (unsigned)HW))
                    v = __ldg(qb + row * HW + col);
            }
            qvs[j] = v;
        }
    }
    __syncthreads();

    // ---- main loop: 9 float4 outputs per thread (one per kk) ----
    float4* out4 = (float4*)out + (size_t)bc * 9216 + q * 256 + tid;
    const int lrow = tid >> 4;                     // 0..15
    const int col  = (tid & 15) << 2;              // 0..60, 16B aligned

    #pragma unroll
    for (int dr = 0; dr < 3; dr++) {
        const float* wp = &ktile[(lrow + dr) * KP + col];
        const float4 a = *(const float4*)wp;       // w0..w3
        const float2 b = *(const float2*)(wp + 4); // w4,w5
        const float w0 = a.x, w1 = a.y, w2 = a.z, w3 = a.w, w4 = b.x, w5 = b.y;

        #pragma unroll
        for (int dc = 0; dc < 3; dc++) {
            const int kk   = 3 * dr + dc;
            const int f    = kk * LSZ + q1024 + (tid << 2);
            const unsigned lp0  = (unsigned)f / 9u;          // mul-hi
            const int      rem  = f - (int)lp0 * 9;          // 0..8
            const unsigned base = (unsigned)(kk * LSZ + q1024) / 9u;
            const int      idx  = kk * QW + (int)(lp0 - base);
            const float q0 = qvs[idx];
            const float qn = qvs[idx + 1];

            float4 o;
            o.x = (dc == 0 ? w0 : dc == 1 ? w1 : w2) * q0;
            o.y = (dc == 0 ? w1 : dc == 1 ? w2 : w3) * (rem >= 8 ? qn : q0);
            o.z = (dc == 0 ? w2 : dc == 1 ? w3 : w4) * (rem >= 7 ? qn : q0);
            o.w = (dc == 0 ? w3 : dc == 1 ? w4 : w5) * (rem >= 6 ? qn : q0);
            __stcs(&out4[kk * 1024], o);           // streaming store
        }
    }
}

extern "C" void kernel_launch(void* const* d_in, const int* in_sizes, int n_in,
                              void* d_out, int out_size) {
    const float* key   = (const float*)d_in[0];
    const float* query = (const float*)d_in[1];
    float* out = (float*)d_out;

    appearance_kernel<<<8192, 256>>>(key, query, out);
}

// round 8
// speedup vs baseline: 1.0998x; 1.0037x over previous
#include <cuda_runtime.h>
#include <cstdint>

// Problem: B=8, C=256, H=W=64, K=3, pad=1, stride=1
// out_flat[f] = keyflat[f] * qv[f/9], f in [0, 9*4096) per (b,c) slice
//   keyflat[f] = zero-padded key at (l>>6 + kk/3 - 1, (l&63) + kk%3 - 1)
//   qv[l']     = zero-padded query at fq = 9*l'+4 (same patch formula)
// CTA = (slice bc, quarter q): handles l in [q*1024, q*1024+1024), all 9 kk.
// Index math: f = f0 + 4096*kk, 4096 = 9*455 + 1 ->
//   lp0 = a0 + 455*kk + [r0+kk>=9],  rem = r0+kk - 9*[r0+kk>=9]
//   idx into per-kk qv window: kk*QW + (a0-b0) + [r0+kk>=9] - [s0+kk>=9]
#define HW   64
#define KP   68                 // key tile pitch (1 left halo + 64 + 3 right pad)
#define KR   18                 // image rows q*16-1 .. q*16+16
#define QW   116                // qv window entries per kk
#define QVT  (9 * QW)           // 1044 words
#define LSZ  4096

__global__ void __launch_bounds__(256)
appearance_kernel(const float* __restrict__ key,
                  const float* __restrict__ query,
                  float* __restrict__ out) {
    __shared__ alignas(16) float ktile[KR * KP];   // 4896 B
    __shared__ alignas(16) float qvs[QVT];         // 4176 B

    const int tid = threadIdx.x;
    const int bid = blockIdx.x;        // 0..8191
    const int bc  = bid >> 2;          // slice 0..2047
    const int q   = bid & 3;           // quarter 0..3
    const int q1024 = q << 10;

    const float*  kb  = key   + (size_t)bc * LSZ;
    const float4* kb4 = (const float4*)kb;
    const float*  qb  = query + (size_t)bc * LSZ;

    // ---- zero halo columns (cols 0, 65, 66, 67 of all 18 rows) ----
    if (tid < KR * 4) {
        const int lr = tid >> 2, hc = tid & 3;
        ktile[lr * KP + (hc == 0 ? 0 : 64 + hc)] = 0.0f;
    }

    // ---- key tile: local row lr = image row (q*16 - 1 + lr) ----
    #pragma unroll
    for (int k = 0; k < 2; k++) {
        const int i = tid + k * 256;               // need 288 of 512
        if (i < KR * 16) {
            const int lr = i >> 4, c4 = i & 15;
            const int ir = q * 16 - 1 + lr;
            float4 v = make_float4(0.f, 0.f, 0.f, 0.f);
            if ((unsigned)ir < (unsigned)HW) v = kb4[ir * 16 + c4];
            float* p = &ktile[lr * KP + 1 + c4 * 4];
            p[0] = v.x; p[1] = v.y; p[2] = v.z; p[3] = v.w;
        }
    }

    // ---- qv windows: qvs[kk*QW + j] = qv[base(kk) + j] ----
    #pragma unroll
    for (int k = 0; k < 5; k++) {
        const int j = tid + k * 256;               // need 1044 of 1280
        if (j < QVT) {
            const int kk = (unsigned)j / QW;
            const int jj = j - kk * QW;
            const int lp = (unsigned)(kk * LSZ + q1024) / 9u + jj;
            float v = 0.0f;
            if (lp < LSZ) {
                const int fq  = 9 * lp + 4;
                const int kkq = fq >> 12;
                const int lq  = fq & 4095;
                const int row = (lq >> 6) + kkq / 3 - 1;
                const int col = (lq & 63) + kkq % 3 - 1;
                if (((unsigned)row < (unsigned)HW) & ((unsigned)col < (unsigned)HW))
                    v = __ldg(qb + row * HW + col);
            }
            qvs[j] = v;
        }
    }
    __syncthreads();

    // ---- per-thread division done ONCE; loop uses adds/compares only ----
    const int f0 = q1024 + (tid << 2);
    const unsigned a0 = (unsigned)f0 / 9u;         // one mul-hi div
    const int r0 = f0 - (int)a0 * 9;               // 0..8
    const unsigned b0 = (unsigned)q1024 / 9u;
    const int s0 = q1024 - (int)b0 * 9;            // 0..8
    const int d0 = (int)(a0 - b0);                 // 0..113

    float4* out4 = (float4*)out + (size_t)bc * 9216 + q * 256 + tid;
    const int lrow = tid >> 4;                     // 0..15
    const int col  = (tid & 15) << 2;              // 0..60, 16B aligned

    #pragma unroll
    for (int dr = 0; dr < 3; dr++) {
        const float* wp = &ktile[(lrow + dr) * KP + col];
        const float4 a = *(const float4*)wp;       // w0..w3
        const float2 b = *(const float2*)(wp + 4); // w4,w5
        const float w0 = a.x, w1 = a.y, w2 = a.z, w3 = a.w, w4 = b.x, w5 = b.y;

        #pragma unroll
        for (int dc = 0; dc < 3; dc++) {
            const int kk = 3 * dr + dc;
            const int rk = r0 + kk;                // 0..16
            const int cr = (rk >= 9) ? 1 : 0;
            const int rem = rk - (cr ? 9 : 0);     // 0..8
            const int cs = (s0 + kk >= 9) ? 1 : 0;
            const int idx = kk * QW + d0 + cr - cs;
            const float q0 = qvs[idx];
            const float qn = qvs[idx + 1];

            float4 o;
            o.x = (dc == 0 ? w0 : dc == 1 ? w1 : w2) * q0;
            o.y = (dc == 0 ? w1 : dc == 1 ? w2 : w3) * (rem >= 8 ? qn : q0);
            o.z = (dc == 0 ? w2 : dc == 1 ? w3 : w4) * (rem >= 7 ? qn : q0);
            o.w = (dc == 0 ? w3 : dc == 1 ? w4 : w5) * (rem >= 6 ? qn : q0);
            __stcs(&out4[kk * 1024], o);           // streaming store
        }
    }
}

extern "C" void kernel_launch(void* const* d_in, const int* in_sizes, int n_in,
                              void* d_out, int out_size) {
    const float* key   = (const float*)d_in[0];
    const float* query = (const float*)d_in[1];
    float* out = (float*)d_out;

    appearance_kernel<<<8192, 256>>>(key, query, out);
}